// round 5
// baseline (speedup 1.0000x reference)
#include <cuda_runtime.h>
#include <math.h>

// Problem shapes (fixed by the dataset)
#define N_SRC 8
#define B 4
#define T 2048
#define H 2048
#define THREADS 512          // H/4 floats per thread
#define ROWS 4               // t-rows per CTA (L2-prefetch pipeline)
#define EPS 1e-6f
#define PITCH 16

__device__ __forceinline__ void prefetch_l2(const void* p) {
    asm volatile("prefetch.global.L2 [%0];" :: "l"(p));
}

// ---------------------------------------------------------------------------
// One CTA per 4 consecutive (b,t) rows.
//  - 8 rows of values in registers (float4/thread per n), front-batched LDG
//  - L2 prefetch 2 rows ahead (DRAM busy through the reduce/softmax tail)
//  - fold-reduce (16 SHFL/thread) + single barrier w/ double-buffered red[]
//  - cbias_n = (q . bias_n)/sqrt(H) computed per-CTA in row 0 (no prelude)
// ---------------------------------------------------------------------------
__global__ __launch_bounds__(THREADS, 2)
void router_kernel(const float* __restrict__ values,
                   const float* __restrict__ wq,
                   const float* __restrict__ bias,
                   const int* __restrict__ pos_ptr,
                   float* __restrict__ out_routed,   // [B][T][H]
                   float* __restrict__ out_alpha) {  // [B][T][N_SRC]
    const int t0   = blockIdx.x * ROWS;
    const int b    = blockIdx.y;
    const int tid  = threadIdx.x;
    const int warp = tid >> 5, lane = tid & 31;
    const int pos  = pos_ptr ? *pos_ptr : N_SRC;
    const int j    = tid << 2;                      // float index within row

    __shared__ float red[2][16 * PITCH];            // double-buffered per-warp totals
    __shared__ float cbred[16][N_SRC + 1];          // row-0 cbias per-warp totals
    __shared__ float cb_s[N_SRC];

    const float4 q = *(const float4*)(wq + (size_t)pos * H + j);
    const size_t nstr     = (size_t)B * T * H;      // n stride in values
    const size_t rowstart = ((size_t)b * T + t0) * (size_t)H;

    // prefetch mapping: thread tid covers one 128B line of the target row
    const int pf_n   = tid >> 6;
    const int pf_off = (tid & 63) << 5;             // *32 floats = 128B line
    const float* pf0 = values + rowstart + (size_t)pf_n * nstr + pf_off;

    // prologue: rows 1 and 2 into L2
    prefetch_l2(pf0 + H);
    prefetch_l2(pf0 + 2 * H);

    const float inv_sqrt_h = rsqrtf((float)H);
    const float inv_h = 1.0f / (float)H;

    #pragma unroll
    for (int i = 0; i < ROWS; i++) {
        const size_t rbase = rowstart + (size_t)i * H;

        // front-batched loads of this row (8 x LDG.128)
        float4 v[N_SRC];
        #pragma unroll
        for (int n = 0; n < N_SRC; n++)
            v[n] = __ldcs((const float4*)(values + rbase + (size_t)n * nstr + j));

        // prefetch row i+2 into L2
        if (i + 2 < ROWS)
            prefetch_l2(pf0 + (size_t)(i + 2) * H);

        // per-thread partials: val[0..7] = sum(v^2), val[8..15] = q.v
        float val[16];
        #pragma unroll
        for (int n = 0; n < N_SRC; n++) {
            const float4 x = v[n];
            val[n]     = x.x*x.x + x.y*x.y + x.z*x.z + x.w*x.w;
            val[8 + n] = q.x*x.x + q.y*x.y + q.z*x.z + q.w*x.w;
        }

        // row 0 only: cbias partials + full butterfly + per-warp write
        if (i == 0) {
            float cb[N_SRC];
            #pragma unroll
            for (int n = 0; n < N_SRC; n++) {
                const float4 bv = __ldg((const float4*)(bias + (size_t)n * H + j));
                cb[n] = q.x*bv.x + q.y*bv.y + q.z*bv.z + q.w*bv.w;
            }
            #pragma unroll
            for (int n = 0; n < N_SRC; n++) {
                #pragma unroll
                for (int o = 16; o; o >>= 1)
                    cb[n] += __shfl_xor_sync(0xffffffffu, cb[n], o);
            }
            if (lane == 0) {
                #pragma unroll
                for (int n = 0; n < N_SRC; n++)
                    cbred[warp][n] = cb[n];
            }
        }

        // fold-reduce: halve value count each level (16 SHFL total)
        {   // o=16: keep 8
            const bool bit = (lane & 16) != 0;
            #pragma unroll
            for (int k = 0; k < 8; k++) {
                const float send = bit ? val[k] : val[8 + k];
                const float recv = __shfl_xor_sync(0xffffffffu, send, 16);
                val[k] = (bit ? val[8 + k] : val[k]) + recv;
            }
        }
        {   // o=8: keep 4
            const bool bit = (lane & 8) != 0;
            #pragma unroll
            for (int k = 0; k < 4; k++) {
                const float send = bit ? val[k] : val[4 + k];
                const float recv = __shfl_xor_sync(0xffffffffu, send, 8);
                val[k] = (bit ? val[4 + k] : val[k]) + recv;
            }
        }
        {   // o=4: keep 2
            const bool bit = (lane & 4) != 0;
            #pragma unroll
            for (int k = 0; k < 2; k++) {
                const float send = bit ? val[k] : val[2 + k];
                const float recv = __shfl_xor_sync(0xffffffffu, send, 4);
                val[k] = (bit ? val[2 + k] : val[k]) + recv;
            }
        }
        float t;
        {   // o=2: keep 1
            const bool bit = (lane & 2) != 0;
            const float send = bit ? val[0] : val[1];
            const float recv = __shfl_xor_sync(0xffffffffu, send, 2);
            t = (bit ? val[1] : val[0]) + recv;
        }
        t += __shfl_xor_sync(0xffffffffu, t, 1);
        // lane L now holds warp total of value index (L>>1)

        float* rb = red[i & 1];
        if ((lane & 1) == 0)
            rb[warp * PITCH + (lane >> 1)] = t;
        __syncthreads();                            // the only barrier per row

        // every warp redundantly sums the 16 columns
        float tk = 0.f;
        if (lane < 16) {
            #pragma unroll
            for (int w = 0; w < 16; w++)
                tk += rb[w * PITCH + lane];
        }

        // row 0: finish cbias column-sum, persist to cb_s
        float cbv = 0.f;
        if (i == 0) {
            if (lane < N_SRC) {
                #pragma unroll
                for (int w = 0; w < 16; w++)
                    cbv += cbred[w][lane];
                cbv *= inv_sqrt_h;
                if (warp == 0) cb_s[lane] = cbv;    // read by rows 1..3 after their barrier
            }
        }

        // per-thread softmax over 8 scalars (gather via shuffle)
        float alpha[N_SRC];
        {
            float sc[N_SRC];
            float m = -1e30f;
            #pragma unroll
            for (int n = 0; n < N_SRC; n++) {
                const float sumsq = __shfl_sync(0xffffffffu, tk, n);
                const float dotq  = __shfl_sync(0xffffffffu, tk, 8 + n);
                const float cbn   = (i == 0) ? __shfl_sync(0xffffffffu, cbv, n)
                                             : cb_s[n];
                const float inv   = rsqrtf(sumsq * inv_h + EPS);
                sc[n] = dotq * inv * inv_sqrt_h + cbn;
                m = fmaxf(m, sc[n]);
            }
            float sum = 0.f;
            #pragma unroll
            for (int n = 0; n < N_SRC; n++) { sc[n] = __expf(sc[n] - m); sum += sc[n]; }
            const float r = 1.0f / sum;
            #pragma unroll
            for (int n = 0; n < N_SRC; n++) alpha[n] = sc[n] * r;
        }

        // routed = sum_n alpha_n * v_n  (register-resident), streaming store
        float4 o;
        o.x = alpha[0]*v[0].x; o.y = alpha[0]*v[0].y;
        o.z = alpha[0]*v[0].z; o.w = alpha[0]*v[0].w;
        #pragma unroll
        for (int n = 1; n < N_SRC; n++) {
            o.x += alpha[n]*v[n].x;
            o.y += alpha[n]*v[n].y;
            o.z += alpha[n]*v[n].z;
            o.w += alpha[n]*v[n].w;
        }
        __stcs((float4*)(out_routed + rbase + j), o);

        if (tid < N_SRC)
            out_alpha[((size_t)b * T + t0 + i) * N_SRC + tid] = alpha[tid];
    }
}

// ---------------------------------------------------------------------------
// kernel_launch
// inputs: [0] values f32 [8,4,2048,2048], [1] w_query f32 [12,2048],
//         [2] key_pos_bias f32 [12,2048], [3] position i32 scalar
// output: routed f32 [4,2048,2048] followed by alpha f32 [4,2048,8]
// ---------------------------------------------------------------------------
extern "C" void kernel_launch(void* const* d_in, const int* in_sizes, int n_in,
                              void* d_out, int out_size) {
    const float* values = (const float*)d_in[0];
    const float* wq     = (const float*)d_in[1];
    const float* bias   = (const float*)d_in[2];
    const int*   pos    = (n_in > 3) ? (const int*)d_in[3] : nullptr;

    float* out_routed = (float*)d_out;
    float* out_alpha  = (float*)d_out + (size_t)B * T * H;

    dim3 grid(T / ROWS, B);
    router_kernel<<<grid, THREADS>>>(values, wq, bias, pos, out_routed, out_alpha);
}

// round 6
// speedup vs baseline: 1.0335x; 1.0335x over previous
#include <cuda_runtime.h>
#include <math.h>

// Problem shapes (fixed by the dataset)
#define N_SRC 8
#define B 4
#define T 2048
#define H 2048
#define THREADS 512          // H/4 floats per thread
#define NROWS (B * T)        // 8192 (b,t) rows total
#define EPS 1e-6f
#define PITCH 16
#define CTAS_PER_SM 2

// Per-n constant: (w_query[pos] . key_pos_bias[n]) / sqrt(H)
__device__ float g_cbias[N_SRC];

// ---------------------------------------------------------------------------
// Prelude: g_cbias[n] = dot(q, bias_n) / sqrt(H)   (reads 128 KB once)
// ---------------------------------------------------------------------------
__global__ void cbias_kernel(const float* __restrict__ wq,
                             const float* __restrict__ bias,
                             const int* __restrict__ pos_ptr) {
    const int n = blockIdx.x;
    const int pos = pos_ptr ? *pos_ptr : N_SRC;
    const float* q  = wq   + (size_t)pos * H;
    const float* bn = bias + (size_t)n   * H;

    float s = 0.f;
    for (int i = threadIdx.x; i < H; i += blockDim.x)
        s += q[i] * bn[i];

    #pragma unroll
    for (int o = 16; o; o >>= 1) s += __shfl_xor_sync(0xffffffffu, s, o);

    __shared__ float sm[32];
    if ((threadIdx.x & 31) == 0) sm[threadIdx.x >> 5] = s;
    __syncthreads();
    if (threadIdx.x < 32) {
        const int nw = blockDim.x >> 5;
        float v = (threadIdx.x < nw) ? sm[threadIdx.x] : 0.f;
        #pragma unroll
        for (int o = 16; o; o >>= 1) v += __shfl_xor_sync(0xffffffffu, v, o);
        if (threadIdx.x == 0) g_cbias[n] = v * rsqrtf((float)H);
    }
}

__device__ __forceinline__ void prefetch_l2(const void* p) {
    asm volatile("prefetch.global.L2 [%0];" :: "l"(p));
}

// ---------------------------------------------------------------------------
// Persistent-CTA router: grid = 2*numSMs CTAs, each walks a contiguous strip
// of ~28 (b,t) rows. Per row:
//  - 8 rows of values in registers (float4/thread per n), front-batched LDG
//  - L2 prefetch 2 rows ahead (pipeline spans the whole strip)
//  - fold-reduce (16 SHFL/thread) + 1 barrier/row (double-buffered red[])
// ---------------------------------------------------------------------------
__global__ __launch_bounds__(THREADS, CTAS_PER_SM)
void router_kernel(const float* __restrict__ values,
                   const float* __restrict__ wq,
                   const int* __restrict__ pos_ptr,
                   float* __restrict__ out_routed,   // [B][T][H]
                   float* __restrict__ out_alpha,    // [B][T][N_SRC]
                   int n_cta) {
    const int tid  = threadIdx.x;
    const int warp = tid >> 5, lane = tid & 31;
    const int pos  = pos_ptr ? *pos_ptr : N_SRC;
    const int j    = tid << 2;                      // float index within row

    // contiguous strip assignment: first `rem` CTAs get qn+1 rows
    const int qn  = NROWS / n_cta;
    const int rem = NROWS - qn * n_cta;
    const int cta = blockIdx.x;
    const int r0  = cta * qn + min(cta, rem);
    const int r1  = r0 + qn + (cta < rem ? 1 : 0);

    __shared__ float red[2][16 * PITCH];            // double-buffered per-warp totals
    __shared__ float cb_s[N_SRC];

    if (tid < N_SRC) cb_s[tid] = g_cbias[tid];      // ordered by first row's barrier

    const float4 q = *(const float4*)(wq + (size_t)pos * H + j);
    const size_t nstr = (size_t)B * T * H;          // n stride in values

    // prefetch mapping: thread tid covers one 128B line of the target row
    const int pf_n   = tid >> 6;
    const int pf_off = (tid & 63) << 5;             // *32 floats = 128B line
    const float* pfb = values + (size_t)pf_n * nstr + pf_off;

    // prologue: rows r0+1, r0+2 into L2
    if (r0 + 1 < r1) prefetch_l2(pfb + (size_t)(r0 + 1) * H);
    if (r0 + 2 < r1) prefetch_l2(pfb + (size_t)(r0 + 2) * H);

    const float inv_sqrt_h = rsqrtf((float)H);
    const float inv_h = 1.0f / (float)H;

    for (int r = r0; r < r1; r++) {
        const size_t rbase = (size_t)r * H;

        // front-batched loads of this row (8 x LDG.128)
        float4 v[N_SRC];
        #pragma unroll
        for (int n = 0; n < N_SRC; n++)
            v[n] = __ldcs((const float4*)(values + rbase + (size_t)n * nstr + j));

        // prefetch row r+2 into L2 (in flight through the reduce tail)
        if (r + 2 < r1)
            prefetch_l2(pfb + (size_t)(r + 2) * H);

        // per-thread partials: val[0..7] = sum(v^2), val[8..15] = q.v
        float val[16];
        #pragma unroll
        for (int n = 0; n < N_SRC; n++) {
            const float4 x = v[n];
            val[n]     = x.x*x.x + x.y*x.y + x.z*x.z + x.w*x.w;
            val[8 + n] = q.x*x.x + q.y*x.y + q.z*x.z + q.w*x.w;
        }

        // fold-reduce: halve value count each level (16 SHFL total)
        {   // o=16: keep 8
            const bool bit = (lane & 16) != 0;
            #pragma unroll
            for (int k = 0; k < 8; k++) {
                const float send = bit ? val[k] : val[8 + k];
                const float recv = __shfl_xor_sync(0xffffffffu, send, 16);
                val[k] = (bit ? val[8 + k] : val[k]) + recv;
            }
        }
        {   // o=8: keep 4
            const bool bit = (lane & 8) != 0;
            #pragma unroll
            for (int k = 0; k < 4; k++) {
                const float send = bit ? val[k] : val[4 + k];
                const float recv = __shfl_xor_sync(0xffffffffu, send, 8);
                val[k] = (bit ? val[4 + k] : val[k]) + recv;
            }
        }
        {   // o=4: keep 2
            const bool bit = (lane & 4) != 0;
            #pragma unroll
            for (int k = 0; k < 2; k++) {
                const float send = bit ? val[k] : val[2 + k];
                const float recv = __shfl_xor_sync(0xffffffffu, send, 4);
                val[k] = (bit ? val[2 + k] : val[k]) + recv;
            }
        }
        float t;
        {   // o=2: keep 1
            const bool bit = (lane & 2) != 0;
            const float send = bit ? val[0] : val[1];
            const float recv = __shfl_xor_sync(0xffffffffu, send, 2);
            t = (bit ? val[1] : val[0]) + recv;
        }
        t += __shfl_xor_sync(0xffffffffu, t, 1);
        // lane L now holds warp total of value index (L>>1)

        float* rb = red[r & 1];
        if ((lane & 1) == 0)
            rb[warp * PITCH + (lane >> 1)] = t;
        __syncthreads();                            // the only barrier per row

        // every warp redundantly sums the 16 columns
        float tk = 0.f;
        if (lane < 16) {
            #pragma unroll
            for (int w = 0; w < 16; w++)
                tk += rb[w * PITCH + lane];
        }

        // per-thread softmax over 8 scalars (gather via shuffle)
        float alpha[N_SRC];
        {
            float sc[N_SRC];
            float m = -1e30f;
            #pragma unroll
            for (int n = 0; n < N_SRC; n++) {
                const float sumsq = __shfl_sync(0xffffffffu, tk, n);
                const float dotq  = __shfl_sync(0xffffffffu, tk, 8 + n);
                const float inv   = rsqrtf(sumsq * inv_h + EPS);
                sc[n] = dotq * inv * inv_sqrt_h + cb_s[n];
                m = fmaxf(m, sc[n]);
            }
            float sum = 0.f;
            #pragma unroll
            for (int n = 0; n < N_SRC; n++) { sc[n] = __expf(sc[n] - m); sum += sc[n]; }
            const float r2 = 1.0f / sum;
            #pragma unroll
            for (int n = 0; n < N_SRC; n++) alpha[n] = sc[n] * r2;
        }

        // routed = sum_n alpha_n * v_n  (register-resident), streaming store
        float4 o;
        o.x = alpha[0]*v[0].x; o.y = alpha[0]*v[0].y;
        o.z = alpha[0]*v[0].z; o.w = alpha[0]*v[0].w;
        #pragma unroll
        for (int n = 1; n < N_SRC; n++) {
            o.x += alpha[n]*v[n].x;
            o.y += alpha[n]*v[n].y;
            o.z += alpha[n]*v[n].z;
            o.w += alpha[n]*v[n].w;
        }
        __stcs((float4*)(out_routed + rbase + j), o);

        if (tid < N_SRC)
            out_alpha[(size_t)r * N_SRC + tid] = alpha[tid];
    }
}

// ---------------------------------------------------------------------------
// kernel_launch
// inputs: [0] values f32 [8,4,2048,2048], [1] w_query f32 [12,2048],
//         [2] key_pos_bias f32 [12,2048], [3] position i32 scalar
// output: routed f32 [4,2048,2048] followed by alpha f32 [4,2048,8]
// ---------------------------------------------------------------------------
extern "C" void kernel_launch(void* const* d_in, const int* in_sizes, int n_in,
                              void* d_out, int out_size) {
    const float* values = (const float*)d_in[0];
    const float* wq     = (const float*)d_in[1];
    const float* bias   = (const float*)d_in[2];
    const int*   pos    = (n_in > 3) ? (const int*)d_in[3] : nullptr;

    float* out_routed = (float*)d_out;
    float* out_alpha  = (float*)d_out + (size_t)B * T * H;

    static int n_cta = 0;
    if (n_cta == 0) {
        int dev = 0, nsm = 148;
        cudaGetDevice(&dev);
        cudaDeviceGetAttribute(&nsm, cudaDevAttrMultiProcessorCount, dev);
        n_cta = nsm * CTAS_PER_SM;
    }

    cbias_kernel<<<N_SRC, 256>>>(wq, bias, pos);
    router_kernel<<<n_cta, THREADS>>>(values, wq, pos, out_routed, out_alpha, n_cta);
}

// round 7
// speedup vs baseline: 1.0553x; 1.0210x over previous
#include <cuda_runtime.h>
#include <math.h>

// Problem shapes (fixed by the dataset)
#define N_SRC 8
#define B 4
#define T 2048
#define H 2048
#define THREADS 512          // H/4 floats per thread
#define NROWS (B * T)        // 8192 (b,t) rows total
#define EPS 1e-6f
#define PITCH 16
#define CTAS_PER_SM 2

__device__ __forceinline__ void prefetch_l2(const void* p) {
    asm volatile("prefetch.global.L2 [%0];" :: "l"(p));
}

// ---------------------------------------------------------------------------
// Persistent-CTA router: grid = 2*numSMs CTAs, each walks a contiguous strip
// of ~28 (b,t) rows.
// Prologue (once per CTA): cbias_n = (q . bias_n)/sqrt(H) — bias is 64 KB and
// L2-resident, so 296 redundant reads cost ~19 MB of L2 traffic (~1 us).
// Per row:
//  - 8 rows of values in registers (float4/thread per n), front-batched LDG
//  - L2 prefetch 2 rows ahead (pipeline spans the whole strip)
//  - fold-reduce (16 SHFL/thread) + 1 barrier/row (double-buffered red[])
// ---------------------------------------------------------------------------
__global__ __launch_bounds__(THREADS, CTAS_PER_SM)
void router_kernel(const float* __restrict__ values,
                   const float* __restrict__ wq,
                   const float* __restrict__ bias,
                   const int* __restrict__ pos_ptr,
                   float* __restrict__ out_routed,   // [B][T][H]
                   float* __restrict__ out_alpha,    // [B][T][N_SRC]
                   int n_cta) {
    const int tid  = threadIdx.x;
    const int warp = tid >> 5, lane = tid & 31;
    const int pos  = pos_ptr ? *pos_ptr : N_SRC;
    const int j    = tid << 2;                      // float index within row

    // contiguous strip assignment: first `rem` CTAs get qn+1 rows
    const int qn  = NROWS / n_cta;
    const int rem = NROWS - qn * n_cta;
    const int cta = blockIdx.x;
    const int r0  = cta * qn + min(cta, rem);
    const int r1  = r0 + qn + (cta < rem ? 1 : 0);

    __shared__ float red[2][16 * PITCH];            // double-buffered per-warp totals
    __shared__ float cbred[16][N_SRC + 1];
    __shared__ float cb_s[N_SRC];

    const float4 q = *(const float4*)(wq + (size_t)pos * H + j);
    const size_t nstr = (size_t)B * T * H;          // n stride in values

    // prefetch mapping: thread tid covers one 128B line of the target row
    const int pf_n   = tid >> 6;
    const int pf_off = (tid & 63) << 5;             // *32 floats = 128B line
    const float* pfb = values + (size_t)pf_n * nstr + pf_off;

    const float inv_sqrt_h = rsqrtf((float)H);
    const float inv_h = 1.0f / (float)H;

    // ---- prologue: prefetch first rows + per-CTA cbias ----
    if (r0 + 1 < r1) prefetch_l2(pfb + (size_t)(r0 + 1) * H);
    if (r0 + 2 < r1) prefetch_l2(pfb + (size_t)(r0 + 2) * H);

    {
        float cb[N_SRC];
        #pragma unroll
        for (int n = 0; n < N_SRC; n++) {
            const float4 bv = __ldg((const float4*)(bias + (size_t)n * H + j));
            cb[n] = q.x*bv.x + q.y*bv.y + q.z*bv.z + q.w*bv.w;
        }
        #pragma unroll
        for (int n = 0; n < N_SRC; n++) {
            #pragma unroll
            for (int o = 16; o; o >>= 1)
                cb[n] += __shfl_xor_sync(0xffffffffu, cb[n], o);
        }
        if (lane == 0) {
            #pragma unroll
            for (int n = 0; n < N_SRC; n++)
                cbred[warp][n] = cb[n];
        }
        __syncthreads();
        if (warp == 0 && lane < N_SRC) {
            float s = 0.f;
            #pragma unroll
            for (int w = 0; w < 16; w++) s += cbred[w][lane];
            cb_s[lane] = s * inv_sqrt_h;
        }
        __syncthreads();
    }

    // ---- main loop over this CTA's strip ----
    for (int r = r0; r < r1; r++) {
        const size_t rbase = (size_t)r * H;

        // front-batched loads of this row (8 x LDG.128)
        float4 v[N_SRC];
        #pragma unroll
        for (int n = 0; n < N_SRC; n++)
            v[n] = __ldcs((const float4*)(values + rbase + (size_t)n * nstr + j));

        // prefetch row r+2 into L2 (in flight through the reduce tail)
        if (r + 2 < r1)
            prefetch_l2(pfb + (size_t)(r + 2) * H);

        // per-thread partials: val[0..7] = sum(v^2), val[8..15] = q.v
        float val[16];
        #pragma unroll
        for (int n = 0; n < N_SRC; n++) {
            const float4 x = v[n];
            val[n]     = x.x*x.x + x.y*x.y + x.z*x.z + x.w*x.w;
            val[8 + n] = q.x*x.x + q.y*x.y + q.z*x.z + q.w*x.w;
        }

        // fold-reduce: halve value count each level (16 SHFL total)
        {   // o=16: keep 8
            const bool bit = (lane & 16) != 0;
            #pragma unroll
            for (int k = 0; k < 8; k++) {
                const float send = bit ? val[k] : val[8 + k];
                const float recv = __shfl_xor_sync(0xffffffffu, send, 16);
                val[k] = (bit ? val[8 + k] : val[k]) + recv;
            }
        }
        {   // o=8: keep 4
            const bool bit = (lane & 8) != 0;
            #pragma unroll
            for (int k = 0; k < 4; k++) {
                const float send = bit ? val[k] : val[4 + k];
                const float recv = __shfl_xor_sync(0xffffffffu, send, 8);
                val[k] = (bit ? val[4 + k] : val[k]) + recv;
            }
        }
        {   // o=4: keep 2
            const bool bit = (lane & 4) != 0;
            #pragma unroll
            for (int k = 0; k < 2; k++) {
                const float send = bit ? val[k] : val[2 + k];
                const float recv = __shfl_xor_sync(0xffffffffu, send, 4);
                val[k] = (bit ? val[2 + k] : val[k]) + recv;
            }
        }
        float t;
        {   // o=2: keep 1
            const bool bit = (lane & 2) != 0;
            const float send = bit ? val[0] : val[1];
            const float recv = __shfl_xor_sync(0xffffffffu, send, 2);
            t = (bit ? val[1] : val[0]) + recv;
        }
        t += __shfl_xor_sync(0xffffffffu, t, 1);
        // lane L now holds warp total of value index (L>>1)

        float* rb = red[r & 1];
        if ((lane & 1) == 0)
            rb[warp * PITCH + (lane >> 1)] = t;
        __syncthreads();                            // the only barrier per row

        // every warp redundantly sums the 16 columns
        float tk = 0.f;
        if (lane < 16) {
            #pragma unroll
            for (int w = 0; w < 16; w++)
                tk += rb[w * PITCH + lane];
        }

        // per-thread softmax over 8 scalars (gather via shuffle)
        float alpha[N_SRC];
        {
            float sc[N_SRC];
            float m = -1e30f;
            #pragma unroll
            for (int n = 0; n < N_SRC; n++) {
                const float sumsq = __shfl_sync(0xffffffffu, tk, n);
                const float dotq  = __shfl_sync(0xffffffffu, tk, 8 + n);
                const float inv   = rsqrtf(sumsq * inv_h + EPS);
                sc[n] = dotq * inv * inv_sqrt_h + cb_s[n];
                m = fmaxf(m, sc[n]);
            }
            float sum = 0.f;
            #pragma unroll
            for (int n = 0; n < N_SRC; n++) { sc[n] = __expf(sc[n] - m); sum += sc[n]; }
            const float r2 = 1.0f / sum;
            #pragma unroll
            for (int n = 0; n < N_SRC; n++) alpha[n] = sc[n] * r2;
        }

        // routed = sum_n alpha_n * v_n  (register-resident), streaming store
        float4 o;
        o.x = alpha[0]*v[0].x; o.y = alpha[0]*v[0].y;
        o.z = alpha[0]*v[0].z; o.w = alpha[0]*v[0].w;
        #pragma unroll
        for (int n = 1; n < N_SRC; n++) {
            o.x += alpha[n]*v[n].x;
            o.y += alpha[n]*v[n].y;
            o.z += alpha[n]*v[n].z;
            o.w += alpha[n]*v[n].w;
        }
        __stcs((float4*)(out_routed + rbase + j), o);

        if (tid < N_SRC)
            out_alpha[(size_t)r * N_SRC + tid] = alpha[tid];
    }
}

// ---------------------------------------------------------------------------
// kernel_launch
// inputs: [0] values f32 [8,4,2048,2048], [1] w_query f32 [12,2048],
//         [2] key_pos_bias f32 [12,2048], [3] position i32 scalar
// output: routed f32 [4,2048,2048] followed by alpha f32 [4,2048,8]
// ---------------------------------------------------------------------------
extern "C" void kernel_launch(void* const* d_in, const int* in_sizes, int n_in,
                              void* d_out, int out_size) {
    const float* values = (const float*)d_in[0];
    const float* wq     = (const float*)d_in[1];
    const float* bias   = (const float*)d_in[2];
    const int*   pos    = (n_in > 3) ? (const int*)d_in[3] : nullptr;

    float* out_routed = (float*)d_out;
    float* out_alpha  = (float*)d_out + (size_t)B * T * H;

    static int n_cta = 0;
    if (n_cta == 0) {
        int dev = 0, nsm = 148;
        cudaGetDevice(&dev);
        cudaDeviceGetAttribute(&nsm, cudaDevAttrMultiProcessorCount, dev);
        n_cta = nsm * CTAS_PER_SM;
    }

    router_kernel<<<n_cta, THREADS>>>(values, wq, bias, pos,
                                      out_routed, out_alpha, n_cta);
}